// round 1
// baseline (speedup 1.0000x reference)
#include <cuda_runtime.h>
#include <math.h>

// Problem constants (fixed shapes)
#define B_SZ 4096
#define I_SZ 512
#define H_SZ 512
#define O_SZ 512
#define E_SZ 8
#define C_SZ 8          // GRID_SIZE + ORDER = 5 + 3
#define KF   (I_SZ * 9) // featurized K: silu + 8 spline bases per input = 4608

// -------- Scratch (device globals; no allocation allowed) --------
__device__ float g_F1[(size_t)B_SZ * KF];            // features of x      (75.5 MB)
__device__ float g_F2[(size_t)B_SZ * KF];            // features of h_e    (75.5 MB)
__device__ float g_Wp1[(size_t)E_SZ * H_SZ * KF];    // packed layer-1 W   (75.5 MB)
__device__ float g_Wp2[(size_t)E_SZ * O_SZ * KF];    // packed layer-2 W   (75.5 MB)
__device__ float g_Hbuf[(size_t)B_SZ * H_SZ];        // per-expert hidden  (8 MB)
__device__ float g_gate[(size_t)B_SZ * E_SZ];        // softmax gate probs

// ---------------- zero output ----------------
__global__ void zero_kernel(float* __restrict__ out, int n4) {
    int i = blockIdx.x * blockDim.x + threadIdx.x;
    if (i < n4) reinterpret_cast<float4*>(out)[i] = make_float4(0.f, 0.f, 0.f, 0.f);
}

// ---------------- gate: softmax(x @ gw^T + gb) ----------------
__global__ void gate_kernel(const float* __restrict__ x, const float* __restrict__ gw,
                            const float* __restrict__ gb, float* __restrict__ gate) {
    int warp = (blockIdx.x * blockDim.x + threadIdx.x) >> 5;
    int lane = threadIdx.x & 31;
    if (warp >= B_SZ) return;
    const float* xr = x + (size_t)warp * I_SZ;
    float acc[E_SZ];
#pragma unroll
    for (int e = 0; e < E_SZ; e++) acc[e] = 0.f;
    for (int i = lane; i < I_SZ; i += 32) {
        float xv = xr[i];
#pragma unroll
        for (int e = 0; e < E_SZ; e++) acc[e] += xv * gw[e * I_SZ + i];
    }
#pragma unroll
    for (int e = 0; e < E_SZ; e++) {
#pragma unroll
        for (int o = 16; o > 0; o >>= 1) acc[e] += __shfl_xor_sync(0xffffffffu, acc[e], o);
    }
    if (lane == 0) {
        float mx = -1e30f;
#pragma unroll
        for (int e = 0; e < E_SZ; e++) { acc[e] += gb[e]; mx = fmaxf(mx, acc[e]); }
        float s = 0.f;
#pragma unroll
        for (int e = 0; e < E_SZ; e++) { acc[e] = expf(acc[e] - mx); s += acc[e]; }
        float inv = 1.0f / s;
#pragma unroll
        for (int e = 0; e < E_SZ; e++) gate[(size_t)warp * E_SZ + e] = acc[e] * inv;
    }
}

// ---------------- KAN featurization: x -> [silu(x), N_0..N_7(x)] ----------------
// Knots: t[k] = (k-3)*0.4 - 1, k = 0..11 (matches jnp.arange(-3,9)*0.4 - 1 in fp32)
__device__ __forceinline__ void kan_feat(float x, float* __restrict__ out) {
    float t[12];
#pragma unroll
    for (int k = 0; k < 12; k++) t[k] = (float)(k - 3) * 0.4f - 1.0f;

    float b0[11];
#pragma unroll
    for (int k = 0; k < 11; k++) b0[k] = (x >= t[k] && x < t[k + 1]) ? 1.0f : 0.0f;

    float b1[10];
#pragma unroll
    for (int k = 0; k < 10; k++) {
        float dl = t[k + 1] - t[k], dr = t[k + 2] - t[k + 1];
        b1[k] = (x - t[k]) * (1.0f / dl) * b0[k] + (t[k + 2] - x) * (1.0f / dr) * b0[k + 1];
    }
    float b2[9];
#pragma unroll
    for (int k = 0; k < 9; k++) {
        float dl = t[k + 2] - t[k], dr = t[k + 3] - t[k + 1];
        b2[k] = (x - t[k]) * (1.0f / dl) * b1[k] + (t[k + 3] - x) * (1.0f / dr) * b1[k + 1];
    }
    float b3[8];
#pragma unroll
    for (int k = 0; k < 8; k++) {
        float dl = t[k + 3] - t[k], dr = t[k + 4] - t[k + 1];
        b3[k] = (x - t[k]) * (1.0f / dl) * b2[k] + (t[k + 4] - x) * (1.0f / dr) * b2[k + 1];
    }
    out[0] = x / (1.0f + expf(-x)); // silu
#pragma unroll
    for (int k = 0; k < 8; k++) out[1 + k] = b3[k];
}

__global__ void feat_kernel(const float* __restrict__ in, float* __restrict__ F, int total) {
    int idx = blockIdx.x * blockDim.x + threadIdx.x;
    if (idx >= total) return;
    float v[9];
    kan_feat(in[idx], v);
    float* o = F + (size_t)idx * 9; // F[b][i*9 + j] with idx = b*cols + i
#pragma unroll
    for (int j = 0; j < 9; j++) o[j] = v[j];
}

// ---------------- weight packing: [base_w | spline_w * scaler] ----------------
__global__ void pack_kernel(const float* __restrict__ bw, const float* __restrict__ sw,
                            const float* __restrict__ sc, float* __restrict__ Wp, int total) {
    int idx = blockIdx.x * blockDim.x + threadIdx.x; // idx = (e*N + n)*IN + i
    if (idx >= total) return;
    float b = bw[idx];
    float s = sc[idx];
    const float* sp = sw + (size_t)idx * C_SZ;
    float* o = Wp + (size_t)idx * 9;
    o[0] = b;
#pragma unroll
    for (int c = 0; c < C_SZ; c++) o[1 + c] = sp[c] * s;
}

// ---------------- SGEMM: C[M,N] (+)= A[M,K] @ W[N,K]^T ----------------
#define BM 128
#define BN 64
#define BKK 16
#define TM 8
#define TN 4

__global__ __launch_bounds__(256, 2) void sgemm_kernel(
    const float* __restrict__ A,   // M x K row-major
    const float* __restrict__ Wm,  // N x K row-major
    float* __restrict__ Cout,      // M x N
    const float* __restrict__ gate,// B x E (nullptr => plain store)
    int expert, int M, int N, int K)
{
    __shared__ float As[BKK][BM + 4];
    __shared__ float Bs[BKK][BN + 4];

    const int tid = threadIdx.x;
    const int bm = blockIdx.y * BM;
    const int bn = blockIdx.x * BN;

    const int ty = tid >> 4;      // 0..15 -> m
    const int tx = tid & 15;      // 0..15 -> n
    const int m0 = ty * TM;
    const int n0 = tx * TN;

    const float* Aptr = A + (size_t)bm * K;
    const float* Bptr = Wm + (size_t)bn * K;

    float acc[TM][TN];
#pragma unroll
    for (int i = 0; i < TM; i++)
#pragma unroll
        for (int j = 0; j < TN; j++) acc[i][j] = 0.f;

    for (int k0 = 0; k0 < K; k0 += BKK) {
        // A tile: 128 rows x 16 k = 512 float4 slots, 2 per thread
#pragma unroll
        for (int t = 0; t < 2; t++) {
            int s = tid + t * 256;
            int m = s >> 2;
            int k4 = (s & 3) << 2;
            float4 v = *reinterpret_cast<const float4*>(Aptr + (size_t)m * K + k0 + k4);
            As[k4 + 0][m] = v.x; As[k4 + 1][m] = v.y; As[k4 + 2][m] = v.z; As[k4 + 3][m] = v.w;
        }
        // B tile: 64 rows x 16 k = 256 float4 slots, 1 per thread
        {
            int n = tid >> 2;
            int k4 = (tid & 3) << 2;
            float4 v = *reinterpret_cast<const float4*>(Bptr + (size_t)n * K + k0 + k4);
            Bs[k4 + 0][n] = v.x; Bs[k4 + 1][n] = v.y; Bs[k4 + 2][n] = v.z; Bs[k4 + 3][n] = v.w;
        }
        __syncthreads();
#pragma unroll
        for (int k = 0; k < BKK; k++) {
            float a[TM], b[TN];
#pragma unroll
            for (int i = 0; i < TM; i++) a[i] = As[k][m0 + i];
#pragma unroll
            for (int j = 0; j < TN; j++) b[j] = Bs[k][n0 + j];
#pragma unroll
            for (int i = 0; i < TM; i++)
#pragma unroll
                for (int j = 0; j < TN; j++) acc[i][j] += a[i] * b[j];
        }
        __syncthreads();
    }

    if (gate != nullptr) {
#pragma unroll
        for (int i = 0; i < TM; i++) {
            int row = bm + m0 + i;
            float g = gate[(size_t)row * E_SZ + expert];
            float* cr = Cout + (size_t)row * N + bn + n0;
#pragma unroll
            for (int j = 0; j < TN; j++) cr[j] += g * acc[i][j];
        }
    } else {
#pragma unroll
        for (int i = 0; i < TM; i++) {
            int row = bm + m0 + i;
            float* cr = Cout + (size_t)row * N + bn + n0;
#pragma unroll
            for (int j = 0; j < TN; j++) cr[j] = acc[i][j];
        }
    }
}

// ---------------- launch ----------------
extern "C" void kernel_launch(void* const* d_in, const int* in_sizes, int n_in,
                              void* d_out, int out_size) {
    const float* x        = (const float*)d_in[0];
    const float* gate_w   = (const float*)d_in[1];
    const float* gate_b   = (const float*)d_in[2];
    const float* base_w1  = (const float*)d_in[3];
    const float* spline_w1= (const float*)d_in[4];
    const float* scaler1  = (const float*)d_in[5];
    const float* base_w2  = (const float*)d_in[6];
    const float* spline_w2= (const float*)d_in[7];
    const float* scaler2  = (const float*)d_in[8];
    float* out = (float*)d_out;

    float *pF1, *pF2, *pWp1, *pWp2, *pH, *pG;
    cudaGetSymbolAddress((void**)&pF1, g_F1);
    cudaGetSymbolAddress((void**)&pF2, g_F2);
    cudaGetSymbolAddress((void**)&pWp1, g_Wp1);
    cudaGetSymbolAddress((void**)&pWp2, g_Wp2);
    cudaGetSymbolAddress((void**)&pH, g_Hbuf);
    cudaGetSymbolAddress((void**)&pG, g_gate);

    // 1. zero output
    {
        int n4 = (B_SZ * O_SZ) / 4;
        zero_kernel<<<(n4 + 255) / 256, 256>>>(out, n4);
    }
    // 2. gate softmax
    gate_kernel<<<(B_SZ * 32 + 255) / 256, 256>>>(x, gate_w, gate_b, pG);
    // 3. pack weights (both layers)
    {
        int total = E_SZ * H_SZ * I_SZ;
        pack_kernel<<<(total + 255) / 256, 256>>>(base_w1, spline_w1, scaler1, pWp1, total);
        pack_kernel<<<(total + 255) / 256, 256>>>(base_w2, spline_w2, scaler2, pWp2, total);
    }
    // 4. featurize x (shared across experts)
    {
        int total = B_SZ * I_SZ;
        feat_kernel<<<(total + 255) / 256, 256>>>(x, pF1, total);
    }
    // 5. per-expert pipeline
    dim3 g1(O_SZ / BN, B_SZ / BM); // (8, 32)
    for (int e = 0; e < E_SZ; e++) {
        sgemm_kernel<<<g1, 256>>>(pF1, pWp1 + (size_t)e * H_SZ * KF, pH,
                                  nullptr, e, B_SZ, H_SZ, KF);
        int total = B_SZ * H_SZ;
        feat_kernel<<<(total + 255) / 256, 256>>>(pH, pF2, total);
        sgemm_kernel<<<g1, 256>>>(pF2, pWp2 + (size_t)e * O_SZ * KF, out,
                                  pG, e, B_SZ, O_SZ, KF);
    }
}

// round 3
// speedup vs baseline: 2.6981x; 2.6981x over previous
#include <cuda_runtime.h>
#include <cuda_bf16.h>
#include <math.h>
#include <cstdint>

// Problem constants (fixed shapes)
#define B_SZ 4096
#define I_SZ 512
#define H_SZ 512
#define O_SZ 512
#define E_SZ 8
#define C_SZ 8          // GRID_SIZE + ORDER
#define KF   4608       // featurized K: 512 * 9

// ---------------- scratch (device globals) ----------------
__device__ __nv_bfloat16 g_F1h[(size_t)B_SZ * KF];
__device__ __nv_bfloat16 g_F1l[(size_t)B_SZ * KF];
__device__ __nv_bfloat16 g_F2h[(size_t)B_SZ * KF];
__device__ __nv_bfloat16 g_F2l[(size_t)B_SZ * KF];
__device__ __nv_bfloat16 g_W1h[(size_t)E_SZ * H_SZ * KF];
__device__ __nv_bfloat16 g_W1l[(size_t)E_SZ * H_SZ * KF];
__device__ __nv_bfloat16 g_W2h[(size_t)E_SZ * O_SZ * KF];
__device__ __nv_bfloat16 g_W2l[(size_t)E_SZ * O_SZ * KF];
__device__ float g_H[(size_t)B_SZ * H_SZ];
__device__ float g_gate[(size_t)B_SZ * E_SZ];

// ---------------- PTX helpers (generic features only) ----------------
__device__ __forceinline__ uint32_t smem_u32(const void* p) {
    uint32_t a;
    asm("{ .reg .u64 t; cvta.to.shared.u64 t, %1; cvt.u32.u64 %0, t; }" : "=r"(a) : "l"(p));
    return a;
}
__device__ __forceinline__ void cp16(uint32_t dst, const void* src) {
    asm volatile("cp.async.cg.shared.global [%0], [%1], 16;" :: "r"(dst), "l"(src));
}
__device__ __forceinline__ void cp_commit() { asm volatile("cp.async.commit_group;"); }
template <int N> __device__ __forceinline__ void cp_wait() {
    asm volatile("cp.async.wait_group %0;" :: "n"(N));
}
__device__ __forceinline__ void ldm_x4(uint32_t* r, uint32_t addr) {
    asm volatile("ldmatrix.sync.aligned.m8n8.x4.shared.b16 {%0,%1,%2,%3}, [%4];"
                 : "=r"(r[0]), "=r"(r[1]), "=r"(r[2]), "=r"(r[3]) : "r"(addr));
}
__device__ __forceinline__ void mma_bf16(float* d, const uint32_t* a, const uint32_t* b) {
    asm volatile(
        "mma.sync.aligned.m16n8k16.row.col.f32.bf16.bf16.f32 "
        "{%0,%1,%2,%3}, {%4,%5,%6,%7}, {%8,%9}, {%0,%1,%2,%3};"
        : "+f"(d[0]), "+f"(d[1]), "+f"(d[2]), "+f"(d[3])
        : "r"(a[0]), "r"(a[1]), "r"(a[2]), "r"(a[3]), "r"(b[0]), "r"(b[1]));
}

// ---------------- zero output ----------------
__global__ void zero_kernel(float* __restrict__ out, int n4) {
    int i = blockIdx.x * blockDim.x + threadIdx.x;
    if (i < n4) reinterpret_cast<float4*>(out)[i] = make_float4(0.f, 0.f, 0.f, 0.f);
}

// ---------------- gate softmax ----------------
__global__ void gate_kernel(const float* __restrict__ x, const float* __restrict__ gw,
                            const float* __restrict__ gb, float* __restrict__ gate) {
    int warp = (blockIdx.x * blockDim.x + threadIdx.x) >> 5;
    int lane = threadIdx.x & 31;
    if (warp >= B_SZ) return;
    const float* xr = x + (size_t)warp * I_SZ;
    float acc[E_SZ];
#pragma unroll
    for (int e = 0; e < E_SZ; e++) acc[e] = 0.f;
    for (int i = lane; i < I_SZ; i += 32) {
        float xv = xr[i];
#pragma unroll
        for (int e = 0; e < E_SZ; e++) acc[e] += xv * gw[e * I_SZ + i];
    }
#pragma unroll
    for (int e = 0; e < E_SZ; e++) {
#pragma unroll
        for (int o = 16; o > 0; o >>= 1) acc[e] += __shfl_xor_sync(0xffffffffu, acc[e], o);
    }
    if (lane == 0) {
        float mx = -1e30f;
#pragma unroll
        for (int e = 0; e < E_SZ; e++) { acc[e] += gb[e]; mx = fmaxf(mx, acc[e]); }
        float s = 0.f;
#pragma unroll
        for (int e = 0; e < E_SZ; e++) { acc[e] = expf(acc[e] - mx); s += acc[e]; }
        float inv = 1.0f / s;
#pragma unroll
        for (int e = 0; e < E_SZ; e++) gate[(size_t)warp * E_SZ + e] = acc[e] * inv;
    }
}

// ---------------- KAN featurization ----------------
__device__ __forceinline__ void kan_feat(float x, float* __restrict__ out) {
    float t[12];
#pragma unroll
    for (int k = 0; k < 12; k++) t[k] = (float)(k - 3) * 0.4f - 1.0f;
    float b0[11];
#pragma unroll
    for (int k = 0; k < 11; k++) b0[k] = (x >= t[k] && x < t[k + 1]) ? 1.0f : 0.0f;
    float b1[10];
#pragma unroll
    for (int k = 0; k < 10; k++) {
        float dl = t[k + 1] - t[k], dr = t[k + 2] - t[k + 1];
        b1[k] = (x - t[k]) * (1.0f / dl) * b0[k] + (t[k + 2] - x) * (1.0f / dr) * b0[k + 1];
    }
    float b2[9];
#pragma unroll
    for (int k = 0; k < 9; k++) {
        float dl = t[k + 2] - t[k], dr = t[k + 3] - t[k + 1];
        b2[k] = (x - t[k]) * (1.0f / dl) * b1[k] + (t[k + 3] - x) * (1.0f / dr) * b1[k + 1];
    }
    float b3[8];
#pragma unroll
    for (int k = 0; k < 8; k++) {
        float dl = t[k + 3] - t[k], dr = t[k + 4] - t[k + 1];
        b3[k] = (x - t[k]) * (1.0f / dl) * b2[k] + (t[k + 4] - x) * (1.0f / dr) * b2[k + 1];
    }
    out[0] = x / (1.0f + expf(-x));
#pragma unroll
    for (int k = 0; k < 8; k++) out[1 + k] = b3[k];
}

__global__ void featbf_kernel(const float* __restrict__ in,
                              __nv_bfloat16* __restrict__ Fh,
                              __nv_bfloat16* __restrict__ Fl, int total) {
    int idx = blockIdx.x * blockDim.x + threadIdx.x;
    if (idx >= total) return;
    float v[9];
    kan_feat(in[idx], v);
    __nv_bfloat16* oh = Fh + (size_t)idx * 9;
    __nv_bfloat16* ol = Fl + (size_t)idx * 9;
#pragma unroll
    for (int j = 0; j < 9; j++) {
        __nv_bfloat16 h = __float2bfloat16(v[j]);
        oh[j] = h;
        ol[j] = __float2bfloat16(v[j] - __bfloat162float(h));
    }
}

// ---------------- weight packing (bf16 hi/lo) ----------------
__global__ void packbf_kernel(const float* __restrict__ bw, const float* __restrict__ sw,
                              const float* __restrict__ sc,
                              __nv_bfloat16* __restrict__ Wh, __nv_bfloat16* __restrict__ Wl,
                              int total) {
    int idx = blockIdx.x * blockDim.x + threadIdx.x; // (e*N + n)*IN + i
    if (idx >= total) return;
    float vals[9];
    vals[0] = bw[idx];
    float s = sc[idx];
    const float* sp = sw + (size_t)idx * C_SZ;
#pragma unroll
    for (int c = 0; c < C_SZ; c++) vals[1 + c] = sp[c] * s;
    __nv_bfloat16* oh = Wh + (size_t)idx * 9;
    __nv_bfloat16* ol = Wl + (size_t)idx * 9;
#pragma unroll
    for (int j = 0; j < 9; j++) {
        __nv_bfloat16 h = __float2bfloat16(vals[j]);
        oh[j] = h;
        ol[j] = __float2bfloat16(vals[j] - __bfloat162float(h));
    }
}

// ---------------- mma.sync split-bf16 GEMM ----------------
// C[4096, 512] (+)= A[4096,KF] @ W[512,KF]^T with A = Ah+Al, W = Wh+Wl
#define BM 128
#define BN 128
#define BK 64
#define NCHUNK (KF / BK)        // 72
#define PLANE_BYTES 16384       // 128 rows * 128 B
#define STAGE_BYTES (4 * PLANE_BYTES)
#define NSTAGE 3
#define GEMM_SMEM (NSTAGE * STAGE_BYTES)   // 196608

__device__ __forceinline__ void load_chunk(uint32_t sb, const __nv_bfloat16* const* gp,
                                           int c, int tid) {
    uint32_t base = sb + (uint32_t)(c % NSTAGE) * STAGE_BYTES;
    int k0 = c * BK;
#pragma unroll
    for (int p = 0; p < 4; p++) {
        const __nv_bfloat16* g = gp[p];
        uint32_t pb = base + p * PLANE_BYTES;
#pragma unroll
        for (int it = 0; it < 4; it++) {
            int idx = tid + it * 256;
            int r = idx >> 3;           // 0..127
            int kk = idx & 7;           // 0..7 (16B chunks)
            uint32_t off = (uint32_t)(r * 128 + kk * 16);
            cp16(pb + (off ^ ((off >> 3) & 0x70)),
                 g + (size_t)r * KF + k0 + kk * 8);
        }
    }
    cp_commit();
}

__global__ __launch_bounds__(256, 1) void kan_gemm(
    const __nv_bfloat16* __restrict__ Ah, const __nv_bfloat16* __restrict__ Al,
    const __nv_bfloat16* __restrict__ Bh, const __nv_bfloat16* __restrict__ Bl,
    float* __restrict__ Cout, const float* __restrict__ gate, int expert)
{
    extern __shared__ char smem[];
    uint32_t sb = smem_u32(smem);
    const int tid = threadIdx.x;
    const int wid = tid >> 5, lane = tid & 31;
    const int warp_m = wid & 1;       // 0..1 -> 64-row slab
    const int warp_n = wid >> 1;      // 0..3 -> 32-col slab
    const int bm = blockIdx.y * BM, bn = blockIdx.x * BN;

    const __nv_bfloat16* gp[4] = {
        Ah + (size_t)bm * KF, Al + (size_t)bm * KF,
        Bh + (size_t)bn * KF, Bl + (size_t)bn * KF
    };

    // per-lane ldmatrix address components (offsets within a plane)
    // A (x4 per 16-row tile): lanes 0-15 -> rows 0-15, lanes 16-31 -> +16B in k
    uint32_t a_row[4], a_xor[4];
#pragma unroll
    for (int mt = 0; mt < 4; mt++) {
        int r = warp_m * 64 + mt * 16 + (lane & 15);
        a_row[mt] = (uint32_t)(r * 128);
        a_xor[mt] = (uint32_t)((r & 7) << 4);
    }
    const uint32_t a_kb = (uint32_t)((lane >> 4) << 4);
    // B (x4 per 16-n pair): groups of 8 lanes -> (n0-7,k0),(n0-7,k8),(n8-15,k0),(n8-15,k8)
    uint32_t b_row[2], b_xor[2];
#pragma unroll
    for (int p = 0; p < 2; p++) {
        int r = warp_n * 32 + p * 16 + ((lane >> 4) << 3) + (lane & 7);
        b_row[p] = (uint32_t)(r * 128);
        b_xor[p] = (uint32_t)((r & 7) << 4);
    }
    const uint32_t b_kb = (uint32_t)(((lane >> 3) & 1) << 4);

    float acc[4][4][4];
#pragma unroll
    for (int mt = 0; mt < 4; mt++)
#pragma unroll
        for (int nt = 0; nt < 4; nt++)
#pragma unroll
            for (int j = 0; j < 4; j++) acc[mt][nt][j] = 0.f;

    load_chunk(sb, gp, 0, tid);
    load_chunk(sb, gp, 1, tid);

    for (int c = 0; c < NCHUNK; c++) {
        if (c + 2 < NCHUNK) cp_wait<1>(); else cp_wait<0>();
        __syncthreads();
        uint32_t stage = sb + (uint32_t)(c % NSTAGE) * STAGE_BYTES;
        uint32_t pAh = stage, pAl = stage + PLANE_BYTES;
        uint32_t pBh = stage + 2 * PLANE_BYTES, pBl = stage + 3 * PLANE_BYTES;

#pragma unroll
        for (int ks = 0; ks < 4; ks++) {
            uint32_t kb = (uint32_t)(ks * 32);
            uint32_t aH[4][4], aL[4][4], bH[4][2], bL[4][2];
#pragma unroll
            for (int mt = 0; mt < 4; mt++) {
                uint32_t off = a_row[mt] + ((kb + a_kb) ^ a_xor[mt]);
                ldm_x4(aH[mt], pAh + off);
                ldm_x4(aL[mt], pAl + off);
            }
#pragma unroll
            for (int p = 0; p < 2; p++) {
                uint32_t off = b_row[p] + ((kb + b_kb) ^ b_xor[p]);
                uint32_t r4[4];
                ldm_x4(r4, pBh + off);
                bH[2 * p][0] = r4[0]; bH[2 * p][1] = r4[1];
                bH[2 * p + 1][0] = r4[2]; bH[2 * p + 1][1] = r4[3];
                ldm_x4(r4, pBl + off);
                bL[2 * p][0] = r4[0]; bL[2 * p][1] = r4[1];
                bL[2 * p + 1][0] = r4[2]; bL[2 * p + 1][1] = r4[3];
            }
#pragma unroll
            for (int mt = 0; mt < 4; mt++)
#pragma unroll
                for (int nt = 0; nt < 4; nt++) {
                    mma_bf16(acc[mt][nt], aH[mt], bH[nt]);
                    mma_bf16(acc[mt][nt], aH[mt], bL[nt]);
                    mma_bf16(acc[mt][nt], aL[mt], bH[nt]);
                }
        }
        if (c + 2 < NCHUNK) load_chunk(sb, gp, c + 2, tid);
    }

    // ---------------- epilogue ----------------
    const int gm0 = bm + warp_m * 64;
    const int gn0 = bn + warp_n * 32;
#pragma unroll
    for (int mt = 0; mt < 4; mt++) {
        int r0 = gm0 + mt * 16 + (lane >> 2);
        int r1 = r0 + 8;
        float g0 = 0.f, g1 = 0.f;
        if (gate != nullptr) {
            g0 = gate[(size_t)r0 * E_SZ + expert];
            g1 = gate[(size_t)r1 * E_SZ + expert];
        }
#pragma unroll
        for (int nt = 0; nt < 4; nt++) {
            int cc = gn0 + nt * 8 + (lane & 3) * 2;
            float2* p0 = reinterpret_cast<float2*>(Cout + (size_t)r0 * 512 + cc);
            float2* p1 = reinterpret_cast<float2*>(Cout + (size_t)r1 * 512 + cc);
            if (gate != nullptr) {
                float2 v0 = *p0, v1 = *p1;
                v0.x += g0 * acc[mt][nt][0]; v0.y += g0 * acc[mt][nt][1];
                v1.x += g1 * acc[mt][nt][2]; v1.y += g1 * acc[mt][nt][3];
                *p0 = v0; *p1 = v1;
            } else {
                *p0 = make_float2(acc[mt][nt][0], acc[mt][nt][1]);
                *p1 = make_float2(acc[mt][nt][2], acc[mt][nt][3]);
            }
        }
    }
}

// ---------------- launch ----------------
extern "C" void kernel_launch(void* const* d_in, const int* in_sizes, int n_in,
                              void* d_out, int out_size) {
    const float* x         = (const float*)d_in[0];
    const float* gate_w    = (const float*)d_in[1];
    const float* gate_b    = (const float*)d_in[2];
    const float* base_w1   = (const float*)d_in[3];
    const float* spline_w1 = (const float*)d_in[4];
    const float* scaler1   = (const float*)d_in[5];
    const float* base_w2   = (const float*)d_in[6];
    const float* spline_w2 = (const float*)d_in[7];
    const float* scaler2   = (const float*)d_in[8];
    float* out = (float*)d_out;

    __nv_bfloat16 *pF1h, *pF1l, *pF2h, *pF2l, *pW1h, *pW1l, *pW2h, *pW2l;
    float *pH, *pG;
    cudaGetSymbolAddress((void**)&pF1h, g_F1h);
    cudaGetSymbolAddress((void**)&pF1l, g_F1l);
    cudaGetSymbolAddress((void**)&pF2h, g_F2h);
    cudaGetSymbolAddress((void**)&pF2l, g_F2l);
    cudaGetSymbolAddress((void**)&pW1h, g_W1h);
    cudaGetSymbolAddress((void**)&pW1l, g_W1l);
    cudaGetSymbolAddress((void**)&pW2h, g_W2h);
    cudaGetSymbolAddress((void**)&pW2l, g_W2l);
    cudaGetSymbolAddress((void**)&pH, g_H);
    cudaGetSymbolAddress((void**)&pG, g_gate);

    cudaFuncSetAttribute(kan_gemm, cudaFuncAttributeMaxDynamicSharedMemorySize, GEMM_SMEM);

    // 1. zero output
    zero_kernel<<<(B_SZ * O_SZ / 4 + 255) / 256, 256>>>(out, B_SZ * O_SZ / 4);
    // 2. gate softmax
    gate_kernel<<<(B_SZ * 32 + 255) / 256, 256>>>(x, gate_w, gate_b, pG);
    // 3. pack weights
    {
        int total = E_SZ * H_SZ * I_SZ;
        packbf_kernel<<<(total + 255) / 256, 256>>>(base_w1, spline_w1, scaler1, pW1h, pW1l, total);
        packbf_kernel<<<(total + 255) / 256, 256>>>(base_w2, spline_w2, scaler2, pW2h, pW2l, total);
    }
    // 4. featurize x
    {
        int total = B_SZ * I_SZ;
        featbf_kernel<<<(total + 255) / 256, 256>>>(x, pF1h, pF1l, total);
    }
    // 5. per-expert pipeline
    dim3 gg(O_SZ / BN, B_SZ / BM); // (4, 32)
    for (int e = 0; e < E_SZ; e++) {
        kan_gemm<<<gg, 256, GEMM_SMEM>>>(pF1h, pF1l,
                                         pW1h + (size_t)e * H_SZ * KF,
                                         pW1l + (size_t)e * H_SZ * KF,
                                         pH, nullptr, e);
        int total = B_SZ * H_SZ;
        featbf_kernel<<<(total + 255) / 256, 256>>>(pH, pF2h, pF2l, total);
        kan_gemm<<<gg, 256, GEMM_SMEM>>>(pF2h, pF2l,
                                         pW2h + (size_t)e * O_SZ * KF,
                                         pW2l + (size_t)e * O_SZ * KF,
                                         out, pG, e);
    }
}

// round 4
// speedup vs baseline: 3.2866x; 1.2181x over previous
#include <cuda_runtime.h>
#include <cuda_bf16.h>
#include <math.h>
#include <cstdint>

// Problem constants (fixed shapes)
#define B_SZ 4096
#define I_SZ 512
#define H_SZ 512
#define O_SZ 512
#define E_SZ 8
#define C_SZ 8          // GRID_SIZE + ORDER
#define KF   4608       // featurized K: 512 * 9

// ---------------- scratch (device globals) ----------------
__device__ __nv_bfloat16 g_F1h[(size_t)B_SZ * KF];
__device__ __nv_bfloat16 g_F1l[(size_t)B_SZ * KF];
__device__ __nv_bfloat16 g_F2h[(size_t)B_SZ * KF];
__device__ __nv_bfloat16 g_F2l[(size_t)B_SZ * KF];
__device__ __nv_bfloat16 g_W1h[(size_t)E_SZ * H_SZ * KF];
__device__ __nv_bfloat16 g_W1l[(size_t)E_SZ * H_SZ * KF];
__device__ __nv_bfloat16 g_W2h[(size_t)E_SZ * O_SZ * KF];
__device__ __nv_bfloat16 g_W2l[(size_t)E_SZ * O_SZ * KF];
__device__ float g_gate[(size_t)B_SZ * E_SZ];

// ---------------- PTX helpers (generic features only) ----------------
__device__ __forceinline__ uint32_t smem_u32(const void* p) {
    uint32_t a;
    asm("{ .reg .u64 t; cvta.to.shared.u64 t, %1; cvt.u32.u64 %0, t; }" : "=r"(a) : "l"(p));
    return a;
}
__device__ __forceinline__ void cp16(uint32_t dst, const void* src) {
    asm volatile("cp.async.cg.shared.global [%0], [%1], 16;" :: "r"(dst), "l"(src));
}
__device__ __forceinline__ void cp_commit() { asm volatile("cp.async.commit_group;"); }
template <int N> __device__ __forceinline__ void cp_wait() {
    asm volatile("cp.async.wait_group %0;" :: "n"(N));
}
__device__ __forceinline__ void ldm_x4(uint32_t* r, uint32_t addr) {
    asm volatile("ldmatrix.sync.aligned.m8n8.x4.shared.b16 {%0,%1,%2,%3}, [%4];"
                 : "=r"(r[0]), "=r"(r[1]), "=r"(r[2]), "=r"(r[3]) : "r"(addr));
}
__device__ __forceinline__ void mma_bf16(float* d, const uint32_t* a, const uint32_t* b) {
    asm volatile(
        "mma.sync.aligned.m16n8k16.row.col.f32.bf16.bf16.f32 "
        "{%0,%1,%2,%3}, {%4,%5,%6,%7}, {%8,%9}, {%0,%1,%2,%3};"
        : "+f"(d[0]), "+f"(d[1]), "+f"(d[2]), "+f"(d[3])
        : "r"(a[0]), "r"(a[1]), "r"(a[2]), "r"(a[3]), "r"(b[0]), "r"(b[1]));
}

// ---------------- KAN featurization ----------------
__device__ __forceinline__ void kan_feat(float x, float* __restrict__ out) {
    float t[12];
#pragma unroll
    for (int k = 0; k < 12; k++) t[k] = (float)(k - 3) * 0.4f - 1.0f;
    float b0[11];
#pragma unroll
    for (int k = 0; k < 11; k++) b0[k] = (x >= t[k] && x < t[k + 1]) ? 1.0f : 0.0f;
    float b1[10];
#pragma unroll
    for (int k = 0; k < 10; k++) {
        float dl = t[k + 1] - t[k], dr = t[k + 2] - t[k + 1];
        b1[k] = (x - t[k]) * (1.0f / dl) * b0[k] + (t[k + 2] - x) * (1.0f / dr) * b0[k + 1];
    }
    float b2[9];
#pragma unroll
    for (int k = 0; k < 9; k++) {
        float dl = t[k + 2] - t[k], dr = t[k + 3] - t[k + 1];
        b2[k] = (x - t[k]) * (1.0f / dl) * b1[k] + (t[k + 3] - x) * (1.0f / dr) * b1[k + 1];
    }
    float b3[8];
#pragma unroll
    for (int k = 0; k < 8; k++) {
        float dl = t[k + 3] - t[k], dr = t[k + 4] - t[k + 1];
        b3[k] = (x - t[k]) * (1.0f / dl) * b2[k] + (t[k + 4] - x) * (1.0f / dr) * b2[k + 1];
    }
    out[0] = x / (1.0f + expf(-x));
#pragma unroll
    for (int k = 0; k < 8; k++) out[1 + k] = b3[k];
}

// ---------------- gate softmax ----------------
__global__ void gate_kernel(const float* __restrict__ x, const float* __restrict__ gw,
                            const float* __restrict__ gb, float* __restrict__ gate) {
    int warp = (blockIdx.x * blockDim.x + threadIdx.x) >> 5;
    int lane = threadIdx.x & 31;
    if (warp >= B_SZ) return;
    const float* xr = x + (size_t)warp * I_SZ;
    float acc[E_SZ];
#pragma unroll
    for (int e = 0; e < E_SZ; e++) acc[e] = 0.f;
    for (int i = lane; i < I_SZ; i += 32) {
        float xv = xr[i];
#pragma unroll
        for (int e = 0; e < E_SZ; e++) acc[e] += xv * gw[e * I_SZ + i];
    }
#pragma unroll
    for (int e = 0; e < E_SZ; e++) {
#pragma unroll
        for (int o = 16; o > 0; o >>= 1) acc[e] += __shfl_xor_sync(0xffffffffu, acc[e], o);
    }
    if (lane == 0) {
        float mx = -1e30f;
#pragma unroll
        for (int e = 0; e < E_SZ; e++) { acc[e] += gb[e]; mx = fmaxf(mx, acc[e]); }
        float s = 0.f;
#pragma unroll
        for (int e = 0; e < E_SZ; e++) { acc[e] = expf(acc[e] - mx); s += acc[e]; }
        float inv = 1.0f / s;
#pragma unroll
        for (int e = 0; e < E_SZ; e++) gate[(size_t)warp * E_SZ + e] = acc[e] * inv;
    }
}

// ---------------- featurize x (smem-staged vectorized writes) ----------------
__global__ __launch_bounds__(256) void featbf_kernel(const float* __restrict__ in,
                                                     __nv_bfloat16* __restrict__ Fh,
                                                     __nv_bfloat16* __restrict__ Fl) {
    __shared__ __align__(16) unsigned short sh[256 * 9];
    __shared__ __align__(16) unsigned short sl[256 * 9];
    int tid = threadIdx.x;
    int idx = blockIdx.x * 256 + tid;
    float v[9];
    kan_feat(in[idx], v);
#pragma unroll
    for (int j = 0; j < 9; j++) {
        __nv_bfloat16 h = __float2bfloat16(v[j]);
        sh[tid * 9 + j] = __bfloat16_as_ushort(h);
        sl[tid * 9 + j] = __bfloat16_as_ushort(__float2bfloat16(v[j] - __bfloat162float(h)));
    }
    __syncthreads();
    // 256*9*2B = 4608 B = 288 uint4 per plane
    const uint4* s4h = reinterpret_cast<const uint4*>(sh);
    const uint4* s4l = reinterpret_cast<const uint4*>(sl);
    uint4* gh = reinterpret_cast<uint4*>(Fh + (size_t)blockIdx.x * 2304);
    uint4* gl = reinterpret_cast<uint4*>(Fl + (size_t)blockIdx.x * 2304);
    for (int k = tid; k < 288; k += 256) {
        gh[k] = s4h[k];
        gl[k] = s4l[k];
    }
}

// ---------------- weight packing (smem-staged vectorized writes) ----------------
__global__ __launch_bounds__(256) void packbf_kernel(const float* __restrict__ bw,
                                                     const float* __restrict__ sw,
                                                     const float* __restrict__ sc,
                                                     __nv_bfloat16* __restrict__ Wh,
                                                     __nv_bfloat16* __restrict__ Wl) {
    __shared__ __align__(16) unsigned short sh[256 * 9];
    __shared__ __align__(16) unsigned short sl[256 * 9];
    int tid = threadIdx.x;
    int idx = blockIdx.x * 256 + tid; // (e*N + n)*IN + i
    float vals[9];
    vals[0] = bw[idx];
    float s = sc[idx];
    const float* sp = sw + (size_t)idx * C_SZ;
#pragma unroll
    for (int c = 0; c < C_SZ; c++) vals[1 + c] = sp[c] * s;
#pragma unroll
    for (int j = 0; j < 9; j++) {
        __nv_bfloat16 h = __float2bfloat16(vals[j]);
        sh[tid * 9 + j] = __bfloat16_as_ushort(h);
        sl[tid * 9 + j] = __bfloat16_as_ushort(__float2bfloat16(vals[j] - __bfloat162float(h)));
    }
    __syncthreads();
    const uint4* s4h = reinterpret_cast<const uint4*>(sh);
    const uint4* s4l = reinterpret_cast<const uint4*>(sl);
    uint4* gh = reinterpret_cast<uint4*>(Wh + (size_t)blockIdx.x * 2304);
    uint4* gl = reinterpret_cast<uint4*>(Wl + (size_t)blockIdx.x * 2304);
    for (int k = tid; k < 288; k += 256) {
        gh[k] = s4h[k];
        gl[k] = s4l[k];
    }
}

// ---------------- mma.sync split-bf16 GEMM ----------------
// MODE 0: layer-1 — epilogue featurizes H tile, writes F2h/F2l
// MODE 1: layer-2 expert 0 — store g*acc
// MODE 2: layer-2 expert >0 — accumulate g*acc
#define BM 128
#define BN 128
#define BK 64
#define NCHUNK (KF / BK)        // 72
#define PLANE_BYTES 16384       // 128 rows * 128 B
#define STAGE_BYTES (4 * PLANE_BYTES)
#define NSTAGE 3
#define GEMM_SMEM (NSTAGE * STAGE_BYTES)   // 196608
#define HS_STRIDE 130

__device__ __forceinline__ void load_chunk(uint32_t sb, const __nv_bfloat16* const* gp,
                                           int c, int tid) {
    uint32_t base = sb + (uint32_t)(c % NSTAGE) * STAGE_BYTES;
    int k0 = c * BK;
#pragma unroll
    for (int p = 0; p < 4; p++) {
        const __nv_bfloat16* g = gp[p];
        uint32_t pb = base + p * PLANE_BYTES;
#pragma unroll
        for (int it = 0; it < 4; it++) {
            int idx = tid + it * 256;
            int r = idx >> 3;
            int kk = idx & 7;
            uint32_t off = (uint32_t)(r * 128 + kk * 16);
            cp16(pb + (off ^ ((off >> 3) & 0x70)),
                 g + (size_t)r * KF + k0 + kk * 8);
        }
    }
    cp_commit();
}

template <int MODE>
__global__ __launch_bounds__(256, 1) void kan_gemm(
    const __nv_bfloat16* __restrict__ Ah, const __nv_bfloat16* __restrict__ Al,
    const __nv_bfloat16* __restrict__ Bh, const __nv_bfloat16* __restrict__ Bl,
    float* __restrict__ Cout,
    __nv_bfloat16* __restrict__ Fh, __nv_bfloat16* __restrict__ Fl,
    const float* __restrict__ gate, int expert)
{
    extern __shared__ char smem[];
    uint32_t sb = smem_u32(smem);
    const int tid = threadIdx.x;
    const int wid = tid >> 5, lane = tid & 31;
    const int warp_m = wid & 1;       // 0..1 -> 64-row slab
    const int warp_n = wid >> 1;      // 0..3 -> 32-col slab
    const int bm = blockIdx.y * BM, bn = blockIdx.x * BN;

    const __nv_bfloat16* gp[4] = {
        Ah + (size_t)bm * KF, Al + (size_t)bm * KF,
        Bh + (size_t)bn * KF, Bl + (size_t)bn * KF
    };

    uint32_t a_row[4], a_xor[4];
#pragma unroll
    for (int mt = 0; mt < 4; mt++) {
        int r = warp_m * 64 + mt * 16 + (lane & 15);
        a_row[mt] = (uint32_t)(r * 128);
        a_xor[mt] = (uint32_t)((r & 7) << 4);
    }
    const uint32_t a_kb = (uint32_t)((lane >> 4) << 4);
    uint32_t b_row[2], b_xor[2];
#pragma unroll
    for (int p = 0; p < 2; p++) {
        int r = warp_n * 32 + p * 16 + ((lane >> 4) << 3) + (lane & 7);
        b_row[p] = (uint32_t)(r * 128);
        b_xor[p] = (uint32_t)((r & 7) << 4);
    }
    const uint32_t b_kb = (uint32_t)(((lane >> 3) & 1) << 4);

    float acc[4][4][4];
#pragma unroll
    for (int mt = 0; mt < 4; mt++)
#pragma unroll
        for (int nt = 0; nt < 4; nt++)
#pragma unroll
            for (int j = 0; j < 4; j++) acc[mt][nt][j] = 0.f;

    load_chunk(sb, gp, 0, tid);
    load_chunk(sb, gp, 1, tid);

    for (int c = 0; c < NCHUNK; c++) {
        if (c + 2 < NCHUNK) cp_wait<1>(); else cp_wait<0>();
        __syncthreads();
        uint32_t stage = sb + (uint32_t)(c % NSTAGE) * STAGE_BYTES;
        uint32_t pAh = stage, pAl = stage + PLANE_BYTES;
        uint32_t pBh = stage + 2 * PLANE_BYTES, pBl = stage + 3 * PLANE_BYTES;

#pragma unroll
        for (int ks = 0; ks < 4; ks++) {
            uint32_t kb = (uint32_t)(ks * 32);
            uint32_t aH[4][4], aL[4][4], bH[4][2], bL[4][2];
#pragma unroll
            for (int mt = 0; mt < 4; mt++) {
                uint32_t off = a_row[mt] + ((kb + a_kb) ^ a_xor[mt]);
                ldm_x4(aH[mt], pAh + off);
                ldm_x4(aL[mt], pAl + off);
            }
#pragma unroll
            for (int p = 0; p < 2; p++) {
                uint32_t off = b_row[p] + ((kb + b_kb) ^ b_xor[p]);
                uint32_t r4[4];
                ldm_x4(r4, pBh + off);
                bH[2 * p][0] = r4[0]; bH[2 * p][1] = r4[1];
                bH[2 * p + 1][0] = r4[2]; bH[2 * p + 1][1] = r4[3];
                ldm_x4(r4, pBl + off);
                bL[2 * p][0] = r4[0]; bL[2 * p][1] = r4[1];
                bL[2 * p + 1][0] = r4[2]; bL[2 * p + 1][1] = r4[3];
            }
#pragma unroll
            for (int mt = 0; mt < 4; mt++)
#pragma unroll
                for (int nt = 0; nt < 4; nt++) {
                    mma_bf16(acc[mt][nt], aH[mt], bH[nt]);
                    mma_bf16(acc[mt][nt], aH[mt], bL[nt]);
                    mma_bf16(acc[mt][nt], aL[mt], bH[nt]);
                }
        }
        if (c + 2 < NCHUNK) load_chunk(sb, gp, c + 2, tid);
    }

    const int gm0 = bm + warp_m * 64;
    const int gn0 = warp_n * 32;  // column within tile

    if (MODE == 0) {
        // ---- fused featurization epilogue ----
        __syncthreads();   // mainloop smem reads done in all warps
        float* Hs = reinterpret_cast<float*>(smem);
#pragma unroll
        for (int mt = 0; mt < 4; mt++) {
            int r0 = warp_m * 64 + mt * 16 + (lane >> 2);
            int r1 = r0 + 8;
#pragma unroll
            for (int nt = 0; nt < 4; nt++) {
                int cc = gn0 + nt * 8 + (lane & 3) * 2;
                Hs[r0 * HS_STRIDE + cc]     = acc[mt][nt][0];
                Hs[r0 * HS_STRIDE + cc + 1] = acc[mt][nt][1];
                Hs[r1 * HS_STRIDE + cc]     = acc[mt][nt][2];
                Hs[r1 * HS_STRIDE + cc + 1] = acc[mt][nt][3];
            }
        }
        __syncthreads();
        const int row = tid >> 1;          // 0..127
        const int half = tid & 1;          // 0..1 (64 cols each)
        const float* hrow = Hs + row * HS_STRIDE + half * 64;
        // global feature base (element index into bf16 array); byte offset is 2x, 16B-aligned
        size_t gbase = (size_t)(bm + row) * KF + ((size_t)bn + half * 64) * 9;
        uint4* gh = reinterpret_cast<uint4*>(Fh + gbase);
        uint4* gl = reinterpret_cast<uint4*>(Fl + gbase);
#pragma unroll
        for (int b = 0; b < 8; b++) {
            uint32_t hi32[36], lo32[36];
#pragma unroll
            for (int e = 0; e < 8; e++) {
                float f[9];
                kan_feat(hrow[b * 8 + e], f);
#pragma unroll
                for (int j = 0; j < 9; j++) {
                    int p = e * 9 + j;
                    __nv_bfloat16 h = __float2bfloat16(f[j]);
                    uint32_t hb = (uint32_t)__bfloat16_as_ushort(h);
                    uint32_t lb = (uint32_t)__bfloat16_as_ushort(
                        __float2bfloat16(f[j] - __bfloat162float(h)));
                    if ((p & 1) == 0) { hi32[p >> 1] = hb; lo32[p >> 1] = lb; }
                    else { hi32[p >> 1] |= hb << 16; lo32[p >> 1] |= lb << 16; }
                }
            }
#pragma unroll
            for (int q = 0; q < 9; q++) {
                gh[b * 9 + q] = make_uint4(hi32[q * 4], hi32[q * 4 + 1],
                                           hi32[q * 4 + 2], hi32[q * 4 + 3]);
                gl[b * 9 + q] = make_uint4(lo32[q * 4], lo32[q * 4 + 1],
                                           lo32[q * 4 + 2], lo32[q * 4 + 3]);
            }
        }
    } else {
        // ---- layer-2 epilogue: gated store / accumulate ----
#pragma unroll
        for (int mt = 0; mt < 4; mt++) {
            int r0 = gm0 + mt * 16 + (lane >> 2);
            int r1 = r0 + 8;
            float g0 = gate[(size_t)r0 * E_SZ + expert];
            float g1 = gate[(size_t)r1 * E_SZ + expert];
#pragma unroll
            for (int nt = 0; nt < 4; nt++) {
                int cc = bn + gn0 + nt * 8 + (lane & 3) * 2;
                float2* p0 = reinterpret_cast<float2*>(Cout + (size_t)r0 * 512 + cc);
                float2* p1 = reinterpret_cast<float2*>(Cout + (size_t)r1 * 512 + cc);
                if (MODE == 2) {
                    float2 v0 = *p0, v1 = *p1;
                    v0.x += g0 * acc[mt][nt][0]; v0.y += g0 * acc[mt][nt][1];
                    v1.x += g1 * acc[mt][nt][2]; v1.y += g1 * acc[mt][nt][3];
                    *p0 = v0; *p1 = v1;
                } else {
                    *p0 = make_float2(g0 * acc[mt][nt][0], g0 * acc[mt][nt][1]);
                    *p1 = make_float2(g1 * acc[mt][nt][2], g1 * acc[mt][nt][3]);
                }
            }
        }
    }
}

// ---------------- launch ----------------
extern "C" void kernel_launch(void* const* d_in, const int* in_sizes, int n_in,
                              void* d_out, int out_size) {
    const float* x         = (const float*)d_in[0];
    const float* gate_w    = (const float*)d_in[1];
    const float* gate_b    = (const float*)d_in[2];
    const float* base_w1   = (const float*)d_in[3];
    const float* spline_w1 = (const float*)d_in[4];
    const float* scaler1   = (const float*)d_in[5];
    const float* base_w2   = (const float*)d_in[6];
    const float* spline_w2 = (const float*)d_in[7];
    const float* scaler2   = (const float*)d_in[8];
    float* out = (float*)d_out;

    __nv_bfloat16 *pF1h, *pF1l, *pF2h, *pF2l, *pW1h, *pW1l, *pW2h, *pW2l;
    float *pG;
    cudaGetSymbolAddress((void**)&pF1h, g_F1h);
    cudaGetSymbolAddress((void**)&pF1l, g_F1l);
    cudaGetSymbolAddress((void**)&pF2h, g_F2h);
    cudaGetSymbolAddress((void**)&pF2l, g_F2l);
    cudaGetSymbolAddress((void**)&pW1h, g_W1h);
    cudaGetSymbolAddress((void**)&pW1l, g_W1l);
    cudaGetSymbolAddress((void**)&pW2h, g_W2h);
    cudaGetSymbolAddress((void**)&pW2l, g_W2l);
    cudaGetSymbolAddress((void**)&pG, g_gate);

    cudaFuncSetAttribute(kan_gemm<0>, cudaFuncAttributeMaxDynamicSharedMemorySize, GEMM_SMEM);
    cudaFuncSetAttribute(kan_gemm<1>, cudaFuncAttributeMaxDynamicSharedMemorySize, GEMM_SMEM);
    cudaFuncSetAttribute(kan_gemm<2>, cudaFuncAttributeMaxDynamicSharedMemorySize, GEMM_SMEM);

    // 1. gate softmax
    gate_kernel<<<(B_SZ * 32 + 255) / 256, 256>>>(x, gate_w, gate_b, pG);
    // 2. pack weights
    packbf_kernel<<<E_SZ * H_SZ * I_SZ / 256, 256>>>(base_w1, spline_w1, scaler1, pW1h, pW1l);
    packbf_kernel<<<E_SZ * O_SZ * H_SZ / 256, 256>>>(base_w2, spline_w2, scaler2, pW2h, pW2l);
    // 3. featurize x
    featbf_kernel<<<B_SZ * I_SZ / 256, 256>>>(x, pF1h, pF1l);
    // 4. per-expert pipeline
    dim3 gg(O_SZ / BN, B_SZ / BM); // (4, 32)
    for (int e = 0; e < E_SZ; e++) {
        kan_gemm<0><<<gg, 256, GEMM_SMEM>>>(pF1h, pF1l,
                                            pW1h + (size_t)e * H_SZ * KF,
                                            pW1l + (size_t)e * H_SZ * KF,
                                            nullptr, pF2h, pF2l, nullptr, e);
        if (e == 0) {
            kan_gemm<1><<<gg, 256, GEMM_SMEM>>>(pF2h, pF2l,
                                                pW2h + (size_t)e * O_SZ * KF,
                                                pW2l + (size_t)e * O_SZ * KF,
                                                out, nullptr, nullptr, pG, e);
        } else {
            kan_gemm<2><<<gg, 256, GEMM_SMEM>>>(pF2h, pF2l,
                                                pW2h + (size_t)e * O_SZ * KF,
                                                pW2l + (size_t)e * O_SZ * KF,
                                                out, nullptr, nullptr, pG, e);
        }
    }
}

// round 5
// speedup vs baseline: 3.2926x; 1.0018x over previous
#include <cuda_runtime.h>
#include <cuda_bf16.h>
#include <math.h>
#include <cstdint>

// Problem constants (fixed shapes)
#define B_SZ 4096
#define I_SZ 512
#define H_SZ 512
#define O_SZ 512
#define E_SZ 8
#define C_SZ 8          // GRID_SIZE + ORDER
#define KF   4608       // featurized K: 512 * 9

// ---------------- scratch (device globals) ----------------
__device__ __nv_bfloat16 g_F1h[(size_t)B_SZ * KF];
__device__ __nv_bfloat16 g_F1l[(size_t)B_SZ * KF];
__device__ __nv_bfloat16 g_F2h[(size_t)B_SZ * KF];
__device__ __nv_bfloat16 g_F2l[(size_t)B_SZ * KF];
__device__ __nv_bfloat16 g_W1h[(size_t)E_SZ * H_SZ * KF];
__device__ __nv_bfloat16 g_W1l[(size_t)E_SZ * H_SZ * KF];
__device__ __nv_bfloat16 g_W2h[(size_t)E_SZ * O_SZ * KF];
__device__ __nv_bfloat16 g_W2l[(size_t)E_SZ * O_SZ * KF];
__device__ float g_gate[(size_t)B_SZ * E_SZ];

// ---------------- PTX helpers (generic features only) ----------------
__device__ __forceinline__ uint32_t smem_u32(const void* p) {
    uint32_t a;
    asm("{ .reg .u64 t; cvta.to.shared.u64 t, %1; cvt.u32.u64 %0, t; }" : "=r"(a) : "l"(p));
    return a;
}
__device__ __forceinline__ void cp16(uint32_t dst, const void* src) {
    asm volatile("cp.async.cg.shared.global [%0], [%1], 16;" :: "r"(dst), "l"(src));
}
__device__ __forceinline__ void cp_commit() { asm volatile("cp.async.commit_group;"); }
template <int N> __device__ __forceinline__ void cp_wait() {
    asm volatile("cp.async.wait_group %0;" :: "n"(N));
}
__device__ __forceinline__ void ldm_x4(uint32_t* r, uint32_t addr) {
    asm volatile("ldmatrix.sync.aligned.m8n8.x4.shared.b16 {%0,%1,%2,%3}, [%4];"
                 : "=r"(r[0]), "=r"(r[1]), "=r"(r[2]), "=r"(r[3]) : "r"(addr));
}
__device__ __forceinline__ void mma_bf16(float* d, const uint32_t* a, const uint32_t* b) {
    asm volatile(
        "mma.sync.aligned.m16n8k16.row.col.f32.bf16.bf16.f32 "
        "{%0,%1,%2,%3}, {%4,%5,%6,%7}, {%8,%9}, {%0,%1,%2,%3};"
        : "+f"(d[0]), "+f"(d[1]), "+f"(d[2]), "+f"(d[3])
        : "r"(a[0]), "r"(a[1]), "r"(a[2]), "r"(a[3]), "r"(b[0]), "r"(b[1]));
}

// ---------------- KAN featurization ----------------
__device__ __forceinline__ void kan_feat(float x, float* __restrict__ out) {
    float t[12];
#pragma unroll
    for (int k = 0; k < 12; k++) t[k] = (float)(k - 3) * 0.4f - 1.0f;
    float b0[11];
#pragma unroll
    for (int k = 0; k < 11; k++) b0[k] = (x >= t[k] && x < t[k + 1]) ? 1.0f : 0.0f;
    float b1[10];
#pragma unroll
    for (int k = 0; k < 10; k++) {
        float dl = t[k + 1] - t[k], dr = t[k + 2] - t[k + 1];
        b1[k] = (x - t[k]) * (1.0f / dl) * b0[k] + (t[k + 2] - x) * (1.0f / dr) * b0[k + 1];
    }
    float b2[9];
#pragma unroll
    for (int k = 0; k < 9; k++) {
        float dl = t[k + 2] - t[k], dr = t[k + 3] - t[k + 1];
        b2[k] = (x - t[k]) * (1.0f / dl) * b1[k] + (t[k + 3] - x) * (1.0f / dr) * b1[k + 1];
    }
    float b3[8];
#pragma unroll
    for (int k = 0; k < 8; k++) {
        float dl = t[k + 3] - t[k], dr = t[k + 4] - t[k + 1];
        b3[k] = (x - t[k]) * (1.0f / dl) * b2[k] + (t[k + 4] - x) * (1.0f / dr) * b2[k + 1];
    }
    out[0] = x / (1.0f + expf(-x));
#pragma unroll
    for (int k = 0; k < 8; k++) out[1 + k] = b3[k];
}

// ---------------- gate softmax ----------------
__global__ void gate_kernel(const float* __restrict__ x, const float* __restrict__ gw,
                            const float* __restrict__ gb, float* __restrict__ gate) {
    int warp = (blockIdx.x * blockDim.x + threadIdx.x) >> 5;
    int lane = threadIdx.x & 31;
    if (warp >= B_SZ) return;
    const float* xr = x + (size_t)warp * I_SZ;
    float acc[E_SZ];
#pragma unroll
    for (int e = 0; e < E_SZ; e++) acc[e] = 0.f;
    for (int i = lane; i < I_SZ; i += 32) {
        float xv = xr[i];
#pragma unroll
        for (int e = 0; e < E_SZ; e++) acc[e] += xv * gw[e * I_SZ + i];
    }
#pragma unroll
    for (int e = 0; e < E_SZ; e++) {
#pragma unroll
        for (int o = 16; o > 0; o >>= 1) acc[e] += __shfl_xor_sync(0xffffffffu, acc[e], o);
    }
    if (lane == 0) {
        float mx = -1e30f;
#pragma unroll
        for (int e = 0; e < E_SZ; e++) { acc[e] += gb[e]; mx = fmaxf(mx, acc[e]); }
        float s = 0.f;
#pragma unroll
        for (int e = 0; e < E_SZ; e++) { acc[e] = expf(acc[e] - mx); s += acc[e]; }
        float inv = 1.0f / s;
#pragma unroll
        for (int e = 0; e < E_SZ; e++) gate[(size_t)warp * E_SZ + e] = acc[e] * inv;
    }
}

// ---------------- featurize x (smem-staged vectorized writes) ----------------
__global__ __launch_bounds__(256) void featbf_kernel(const float* __restrict__ in,
                                                     __nv_bfloat16* __restrict__ Fh,
                                                     __nv_bfloat16* __restrict__ Fl) {
    __shared__ __align__(16) unsigned short sh[256 * 9];
    __shared__ __align__(16) unsigned short sl[256 * 9];
    int tid = threadIdx.x;
    int idx = blockIdx.x * 256 + tid;
    float v[9];
    kan_feat(in[idx], v);
#pragma unroll
    for (int j = 0; j < 9; j++) {
        __nv_bfloat16 h = __float2bfloat16(v[j]);
        sh[tid * 9 + j] = __bfloat16_as_ushort(h);
        sl[tid * 9 + j] = __bfloat16_as_ushort(__float2bfloat16(v[j] - __bfloat162float(h)));
    }
    __syncthreads();
    const uint4* s4h = reinterpret_cast<const uint4*>(sh);
    const uint4* s4l = reinterpret_cast<const uint4*>(sl);
    uint4* gh = reinterpret_cast<uint4*>(Fh + (size_t)blockIdx.x * 2304);
    uint4* gl = reinterpret_cast<uint4*>(Fl + (size_t)blockIdx.x * 2304);
    for (int k = tid; k < 288; k += 256) {
        gh[k] = s4h[k];
        gl[k] = s4l[k];
    }
}

// ---------------- weight packing (smem-staged vectorized writes) ----------------
__global__ __launch_bounds__(256) void packbf_kernel(const float* __restrict__ bw,
                                                     const float* __restrict__ sw,
                                                     const float* __restrict__ sc,
                                                     __nv_bfloat16* __restrict__ Wh,
                                                     __nv_bfloat16* __restrict__ Wl) {
    __shared__ __align__(16) unsigned short sh[256 * 9];
    __shared__ __align__(16) unsigned short sl[256 * 9];
    int tid = threadIdx.x;
    int idx = blockIdx.x * 256 + tid; // (e*N + n)*IN + i
    float vals[9];
    vals[0] = bw[idx];
    float s = sc[idx];
    const float* sp = sw + (size_t)idx * C_SZ;
#pragma unroll
    for (int c = 0; c < C_SZ; c++) vals[1 + c] = sp[c] * s;
#pragma unroll
    for (int j = 0; j < 9; j++) {
        __nv_bfloat16 h = __float2bfloat16(vals[j]);
        sh[tid * 9 + j] = __bfloat16_as_ushort(h);
        sl[tid * 9 + j] = __bfloat16_as_ushort(__float2bfloat16(vals[j] - __bfloat162float(h)));
    }
    __syncthreads();
    const uint4* s4h = reinterpret_cast<const uint4*>(sh);
    const uint4* s4l = reinterpret_cast<const uint4*>(sl);
    uint4* gh = reinterpret_cast<uint4*>(Wh + (size_t)blockIdx.x * 2304);
    uint4* gl = reinterpret_cast<uint4*>(Wl + (size_t)blockIdx.x * 2304);
    for (int k = tid; k < 288; k += 256) {
        gh[k] = s4h[k];
        gl[k] = s4l[k];
    }
}

// ---------------- mma.sync split-bf16 GEMM ----------------
// MODE 0: layer-1 — epilogue featurizes H tile, writes F2h/F2l
// MODE 1: layer-2 expert 0 — store g*acc
// MODE 2: layer-2 expert >0 — accumulate g*acc
#define BM 128
#define BN 128
#define BK 64
#define NCHUNK (KF / BK)        // 72
#define PLANE_BYTES 16384       // 128 rows * 128 B
#define STAGE_BYTES (4 * PLANE_BYTES)
#define NSTAGE 3
#define GEMM_SMEM (NSTAGE * STAGE_BYTES)   // 196608
#define HS_STRIDE 130

__device__ __forceinline__ void load_chunk(uint32_t sb, const __nv_bfloat16* const* gp,
                                           int c, int tid) {
    uint32_t base = sb + (uint32_t)(c % NSTAGE) * STAGE_BYTES;
    int k0 = c * BK;
#pragma unroll
    for (int p = 0; p < 4; p++) {
        const __nv_bfloat16* g = gp[p];
        uint32_t pb = base + p * PLANE_BYTES;
#pragma unroll
        for (int it = 0; it < 4; it++) {
            int idx = tid + it * 256;
            int r = idx >> 3;
            int kk = idx & 7;
            uint32_t off = (uint32_t)(r * 128 + kk * 16);
            cp16(pb + (off ^ ((off >> 3) & 0x70)),
                 g + (size_t)r * KF + k0 + kk * 8);
        }
    }
    cp_commit();
}

struct Frags {
    uint32_t aH[4][4];
    uint32_t aL[4][4];
    uint32_t bH[4][2];
    uint32_t bL[4][2];
};

template <int MODE>
__global__ __launch_bounds__(256, 1) void kan_gemm(
    const __nv_bfloat16* __restrict__ Ah, const __nv_bfloat16* __restrict__ Al,
    const __nv_bfloat16* __restrict__ Bh, const __nv_bfloat16* __restrict__ Bl,
    float* __restrict__ Cout,
    __nv_bfloat16* __restrict__ Fh, __nv_bfloat16* __restrict__ Fl,
    const float* __restrict__ gate, int expert)
{
    extern __shared__ char smem[];
    uint32_t sb = smem_u32(smem);
    const int tid = threadIdx.x;
    const int wid = tid >> 5, lane = tid & 31;
    const int warp_m = wid & 1;       // 0..1 -> 64-row slab
    const int warp_n = wid >> 1;      // 0..3 -> 32-col slab
    const int bm = blockIdx.y * BM, bn = blockIdx.x * BN;

    const __nv_bfloat16* gp[4] = {
        Ah + (size_t)bm * KF, Al + (size_t)bm * KF,
        Bh + (size_t)bn * KF, Bl + (size_t)bn * KF
    };

    uint32_t a_row[4], a_xor[4];
#pragma unroll
    for (int mt = 0; mt < 4; mt++) {
        int r = warp_m * 64 + mt * 16 + (lane & 15);
        a_row[mt] = (uint32_t)(r * 128);
        a_xor[mt] = (uint32_t)((r & 7) << 4);
    }
    const uint32_t a_kb = (uint32_t)((lane >> 4) << 4);
    uint32_t b_row[2], b_xor[2];
#pragma unroll
    for (int p = 0; p < 2; p++) {
        int r = warp_n * 32 + p * 16 + ((lane >> 4) << 3) + (lane & 7);
        b_row[p] = (uint32_t)(r * 128);
        b_xor[p] = (uint32_t)((r & 7) << 4);
    }
    const uint32_t b_kb = (uint32_t)(((lane >> 3) & 1) << 4);

    float acc[4][4][4];
#pragma unroll
    for (int mt = 0; mt < 4; mt++)
#pragma unroll
        for (int nt = 0; nt < 4; nt++)
#pragma unroll
            for (int j = 0; j < 4; j++) acc[mt][nt][j] = 0.f;

    load_chunk(sb, gp, 0, tid);
    load_chunk(sb, gp, 1, tid);

    Frags fr[2];

    // load the 12 LDSM fragments of (stage, ks) into fr[buf]
    auto load_frags = [&](Frags& f, uint32_t stage, int ks) {
        uint32_t pAh = stage, pAl = stage + PLANE_BYTES;
        uint32_t pBh = stage + 2 * PLANE_BYTES, pBl = stage + 3 * PLANE_BYTES;
        uint32_t kb = (uint32_t)(ks * 32);
#pragma unroll
        for (int mt = 0; mt < 4; mt++) {
            uint32_t off = a_row[mt] + ((kb + a_kb) ^ a_xor[mt]);
            ldm_x4(f.aH[mt], pAh + off);
            ldm_x4(f.aL[mt], pAl + off);
        }
#pragma unroll
        for (int p = 0; p < 2; p++) {
            uint32_t off = b_row[p] + ((kb + b_kb) ^ b_xor[p]);
            uint32_t r4[4];
            ldm_x4(r4, pBh + off);
            f.bH[2 * p][0] = r4[0]; f.bH[2 * p][1] = r4[1];
            f.bH[2 * p + 1][0] = r4[2]; f.bH[2 * p + 1][1] = r4[3];
            ldm_x4(r4, pBl + off);
            f.bL[2 * p][0] = r4[0]; f.bL[2 * p][1] = r4[1];
            f.bL[2 * p + 1][0] = r4[2]; f.bL[2 * p + 1][1] = r4[3];
        }
    };

    for (int c = 0; c < NCHUNK; c++) {
        if (c + 2 < NCHUNK) cp_wait<1>(); else cp_wait<0>();
        __syncthreads();
        uint32_t stage = sb + (uint32_t)(c % NSTAGE) * STAGE_BYTES;

        load_frags(fr[0], stage, 0);
#pragma unroll
        for (int ks = 0; ks < 4; ks++) {
            Frags& cur = fr[ks & 1];
            if (ks < 3) load_frags(fr[(ks & 1) ^ 1], stage, ks + 1);
#pragma unroll
            for (int mt = 0; mt < 4; mt++)
#pragma unroll
                for (int nt = 0; nt < 4; nt++) {
                    mma_bf16(acc[mt][nt], cur.aH[mt], cur.bH[nt]);
                    mma_bf16(acc[mt][nt], cur.aH[mt], cur.bL[nt]);
                    mma_bf16(acc[mt][nt], cur.aL[mt], cur.bH[nt]);
                }
        }
        if (c + 2 < NCHUNK) load_chunk(sb, gp, c + 2, tid);
    }

    const int gm0 = bm + warp_m * 64;
    const int gn0 = warp_n * 32;  // column within tile

    if (MODE == 0) {
        // ---- fused featurization epilogue ----
        __syncthreads();   // mainloop smem reads done in all warps
        float* Hs = reinterpret_cast<float*>(smem);
#pragma unroll
        for (int mt = 0; mt < 4; mt++) {
            int r0 = warp_m * 64 + mt * 16 + (lane >> 2);
            int r1 = r0 + 8;
#pragma unroll
            for (int nt = 0; nt < 4; nt++) {
                int cc = gn0 + nt * 8 + (lane & 3) * 2;
                Hs[r0 * HS_STRIDE + cc]     = acc[mt][nt][0];
                Hs[r0 * HS_STRIDE + cc + 1] = acc[mt][nt][1];
                Hs[r1 * HS_STRIDE + cc]     = acc[mt][nt][2];
                Hs[r1 * HS_STRIDE + cc + 1] = acc[mt][nt][3];
            }
        }
        __syncthreads();
        const int row = tid >> 1;          // 0..127
        const int half = tid & 1;          // 0..1 (64 cols each)
        const float* hrow = Hs + row * HS_STRIDE + half * 64;
        size_t gbase = (size_t)(bm + row) * KF + ((size_t)bn + half * 64) * 9;
        uint4* gh = reinterpret_cast<uint4*>(Fh + gbase);
        uint4* gl = reinterpret_cast<uint4*>(Fl + gbase);
#pragma unroll
        for (int b = 0; b < 8; b++) {
            uint32_t hi32[36], lo32[36];
#pragma unroll
            for (int e = 0; e < 8; e++) {
                float f[9];
                kan_feat(hrow[b * 8 + e], f);
#pragma unroll
                for (int j = 0; j < 9; j++) {
                    int p = e * 9 + j;
                    __nv_bfloat16 h = __float2bfloat16(f[j]);
                    uint32_t hb = (uint32_t)__bfloat16_as_ushort(h);
                    uint32_t lb = (uint32_t)__bfloat16_as_ushort(
                        __float2bfloat16(f[j] - __bfloat162float(h)));
                    if ((p & 1) == 0) { hi32[p >> 1] = hb; lo32[p >> 1] = lb; }
                    else { hi32[p >> 1] |= hb << 16; lo32[p >> 1] |= lb << 16; }
                }
            }
#pragma unroll
            for (int q = 0; q < 9; q++) {
                gh[b * 9 + q] = make_uint4(hi32[q * 4], hi32[q * 4 + 1],
                                           hi32[q * 4 + 2], hi32[q * 4 + 3]);
                gl[b * 9 + q] = make_uint4(lo32[q * 4], lo32[q * 4 + 1],
                                           lo32[q * 4 + 2], lo32[q * 4 + 3]);
            }
        }
    } else {
        // ---- layer-2 epilogue: gated store / accumulate ----
#pragma unroll
        for (int mt = 0; mt < 4; mt++) {
            int r0 = gm0 + mt * 16 + (lane >> 2);
            int r1 = r0 + 8;
            float g0 = gate[(size_t)r0 * E_SZ + expert];
            float g1 = gate[(size_t)r1 * E_SZ + expert];
#pragma unroll
            for (int nt = 0; nt < 4; nt++) {
                int cc = bn + gn0 + nt * 8 + (lane & 3) * 2;
                float2* p0 = reinterpret_cast<float2*>(Cout + (size_t)r0 * 512 + cc);
                float2* p1 = reinterpret_cast<float2*>(Cout + (size_t)r1 * 512 + cc);
                if (MODE == 2) {
                    float2 v0 = *p0, v1 = *p1;
                    v0.x += g0 * acc[mt][nt][0]; v0.y += g0 * acc[mt][nt][1];
                    v1.x += g1 * acc[mt][nt][2]; v1.y += g1 * acc[mt][nt][3];
                    *p0 = v0; *p1 = v1;
                } else {
                    *p0 = make_float2(g0 * acc[mt][nt][0], g0 * acc[mt][nt][1]);
                    *p1 = make_float2(g1 * acc[mt][nt][2], g1 * acc[mt][nt][3]);
                }
            }
        }
    }
}

// ---------------- launch ----------------
extern "C" void kernel_launch(void* const* d_in, const int* in_sizes, int n_in,
                              void* d_out, int out_size) {
    const float* x         = (const float*)d_in[0];
    const float* gate_w    = (const float*)d_in[1];
    const float* gate_b    = (const float*)d_in[2];
    const float* base_w1   = (const float*)d_in[3];
    const float* spline_w1 = (const float*)d_in[4];
    const float* scaler1   = (const float*)d_in[5];
    const float* base_w2   = (const float*)d_in[6];
    const float* spline_w2 = (const float*)d_in[7];
    const float* scaler2   = (const float*)d_in[8];
    float* out = (float*)d_out;

    __nv_bfloat16 *pF1h, *pF1l, *pF2h, *pF2l, *pW1h, *pW1l, *pW2h, *pW2l;
    float *pG;
    cudaGetSymbolAddress((void**)&pF1h, g_F1h);
    cudaGetSymbolAddress((void**)&pF1l, g_F1l);
    cudaGetSymbolAddress((void**)&pF2h, g_F2h);
    cudaGetSymbolAddress((void**)&pF2l, g_F2l);
    cudaGetSymbolAddress((void**)&pW1h, g_W1h);
    cudaGetSymbolAddress((void**)&pW1l, g_W1l);
    cudaGetSymbolAddress((void**)&pW2h, g_W2h);
    cudaGetSymbolAddress((void**)&pW2l, g_W2l);
    cudaGetSymbolAddress((void**)&pG, g_gate);

    cudaFuncSetAttribute(kan_gemm<0>, cudaFuncAttributeMaxDynamicSharedMemorySize, GEMM_SMEM);
    cudaFuncSetAttribute(kan_gemm<1>, cudaFuncAttributeMaxDynamicSharedMemorySize, GEMM_SMEM);
    cudaFuncSetAttribute(kan_gemm<2>, cudaFuncAttributeMaxDynamicSharedMemorySize, GEMM_SMEM);

    // 1. gate softmax
    gate_kernel<<<(B_SZ * 32 + 255) / 256, 256>>>(x, gate_w, gate_b, pG);
    // 2. pack weights
    packbf_kernel<<<E_SZ * H_SZ * I_SZ / 256, 256>>>(base_w1, spline_w1, scaler1, pW1h, pW1l);
    packbf_kernel<<<E_SZ * O_SZ * H_SZ / 256, 256>>>(base_w2, spline_w2, scaler2, pW2h, pW2l);
    // 3. featurize x
    featbf_kernel<<<B_SZ * I_SZ / 256, 256>>>(x, pF1h, pF1l);
    // 4. per-expert pipeline
    dim3 gg(O_SZ / BN, B_SZ / BM); // (4, 32)
    for (int e = 0; e < E_SZ; e++) {
        kan_gemm<0><<<gg, 256, GEMM_SMEM>>>(pF1h, pF1l,
                                            pW1h + (size_t)e * H_SZ * KF,
                                            pW1l + (size_t)e * H_SZ * KF,
                                            nullptr, pF2h, pF2l, nullptr, e);
        if (e == 0) {
            kan_gemm<1><<<gg, 256, GEMM_SMEM>>>(pF2h, pF2l,
                                                pW2h + (size_t)e * O_SZ * KF,
                                                pW2l + (size_t)e * O_SZ * KF,
                                                out, nullptr, nullptr, pG, e);
        } else {
            kan_gemm<2><<<gg, 256, GEMM_SMEM>>>(pF2h, pF2l,
                                                pW2h + (size_t)e * O_SZ * KF,
                                                pW2l + (size_t)e * O_SZ * KF,
                                                out, nullptr, nullptr, pG, e);
        }
    }
}

// round 6
// speedup vs baseline: 3.6220x; 1.1001x over previous
#include <cuda_runtime.h>
#include <cuda_bf16.h>
#include <math.h>
#include <cstdint>

// Problem constants (fixed shapes)
#define B_SZ 4096
#define I_SZ 512
#define H_SZ 512
#define O_SZ 512
#define E_SZ 8
#define C_SZ 8          // GRID_SIZE + ORDER
#define KF   4608       // featurized K: 512 * 9
#define FSTRIDE ((size_t)B_SZ * KF)

// ---------------- scratch (device globals) ----------------
__device__ __nv_bfloat16 g_F1h[FSTRIDE];
__device__ __nv_bfloat16 g_F1l[FSTRIDE];
__device__ __nv_bfloat16 g_F2h[E_SZ * FSTRIDE];   // per-expert, gate-scaled
__device__ __nv_bfloat16 g_F2l[E_SZ * FSTRIDE];
__device__ __nv_bfloat16 g_W1h[(size_t)E_SZ * H_SZ * KF];
__device__ __nv_bfloat16 g_W1l[(size_t)E_SZ * H_SZ * KF];
__device__ __nv_bfloat16 g_W2h[(size_t)E_SZ * O_SZ * KF];
__device__ __nv_bfloat16 g_W2l[(size_t)E_SZ * O_SZ * KF];
__device__ float g_gate[(size_t)B_SZ * E_SZ];

// ---------------- PTX helpers (generic features only) ----------------
__device__ __forceinline__ uint32_t smem_u32(const void* p) {
    uint32_t a;
    asm("{ .reg .u64 t; cvta.to.shared.u64 t, %1; cvt.u32.u64 %0, t; }" : "=r"(a) : "l"(p));
    return a;
}
__device__ __forceinline__ void cp16(uint32_t dst, const void* src) {
    asm volatile("cp.async.cg.shared.global [%0], [%1], 16;" :: "r"(dst), "l"(src));
}
__device__ __forceinline__ void cp_commit() { asm volatile("cp.async.commit_group;"); }
template <int N> __device__ __forceinline__ void cp_wait() {
    asm volatile("cp.async.wait_group %0;" :: "n"(N));
}
__device__ __forceinline__ void ldm_x4(uint32_t* r, uint32_t addr) {
    asm volatile("ldmatrix.sync.aligned.m8n8.x4.shared.b16 {%0,%1,%2,%3}, [%4];"
                 : "=r"(r[0]), "=r"(r[1]), "=r"(r[2]), "=r"(r[3]) : "r"(addr));
}
__device__ __forceinline__ void mma_bf16(float* d, const uint32_t* a, const uint32_t* b) {
    asm volatile(
        "mma.sync.aligned.m16n8k16.row.col.f32.bf16.bf16.f32 "
        "{%0,%1,%2,%3}, {%4,%5,%6,%7}, {%8,%9}, {%0,%1,%2,%3};"
        : "+f"(d[0]), "+f"(d[1]), "+f"(d[2]), "+f"(d[3])
        : "r"(a[0]), "r"(a[1]), "r"(a[2]), "r"(a[3]), "r"(b[0]), "r"(b[1]));
}

// ---------------- KAN featurization ----------------
__device__ __forceinline__ void kan_feat(float x, float* __restrict__ out) {
    float t[12];
#pragma unroll
    for (int k = 0; k < 12; k++) t[k] = (float)(k - 3) * 0.4f - 1.0f;
    float b0[11];
#pragma unroll
    for (int k = 0; k < 11; k++) b0[k] = (x >= t[k] && x < t[k + 1]) ? 1.0f : 0.0f;
    float b1[10];
#pragma unroll
    for (int k = 0; k < 10; k++) {
        float dl = t[k + 1] - t[k], dr = t[k + 2] - t[k + 1];
        b1[k] = (x - t[k]) * (1.0f / dl) * b0[k] + (t[k + 2] - x) * (1.0f / dr) * b0[k + 1];
    }
    float b2[9];
#pragma unroll
    for (int k = 0; k < 9; k++) {
        float dl = t[k + 2] - t[k], dr = t[k + 3] - t[k + 1];
        b2[k] = (x - t[k]) * (1.0f / dl) * b1[k] + (t[k + 3] - x) * (1.0f / dr) * b1[k + 1];
    }
    float b3[8];
#pragma unroll
    for (int k = 0; k < 8; k++) {
        float dl = t[k + 3] - t[k], dr = t[k + 4] - t[k + 1];
        b3[k] = (x - t[k]) * (1.0f / dl) * b2[k] + (t[k + 4] - x) * (1.0f / dr) * b2[k + 1];
    }
    out[0] = x / (1.0f + expf(-x));
#pragma unroll
    for (int k = 0; k < 8; k++) out[1 + k] = b3[k];
}

// ---------------- gate softmax ----------------
__global__ void gate_kernel(const float* __restrict__ x, const float* __restrict__ gw,
                            const float* __restrict__ gb, float* __restrict__ gate) {
    int warp = (blockIdx.x * blockDim.x + threadIdx.x) >> 5;
    int lane = threadIdx.x & 31;
    if (warp >= B_SZ) return;
    const float* xr = x + (size_t)warp * I_SZ;
    float acc[E_SZ];
#pragma unroll
    for (int e = 0; e < E_SZ; e++) acc[e] = 0.f;
    for (int i = lane; i < I_SZ; i += 32) {
        float xv = xr[i];
#pragma unroll
        for (int e = 0; e < E_SZ; e++) acc[e] += xv * gw[e * I_SZ + i];
    }
#pragma unroll
    for (int e = 0; e < E_SZ; e++) {
#pragma unroll
        for (int o = 16; o > 0; o >>= 1) acc[e] += __shfl_xor_sync(0xffffffffu, acc[e], o);
    }
    if (lane == 0) {
        float mx = -1e30f;
#pragma unroll
        for (int e = 0; e < E_SZ; e++) { acc[e] += gb[e]; mx = fmaxf(mx, acc[e]); }
        float s = 0.f;
#pragma unroll
        for (int e = 0; e < E_SZ; e++) { acc[e] = expf(acc[e] - mx); s += acc[e]; }
        float inv = 1.0f / s;
#pragma unroll
        for (int e = 0; e < E_SZ; e++) gate[(size_t)warp * E_SZ + e] = acc[e] * inv;
    }
}

// ---------------- featurize x (smem-staged vectorized writes) ----------------
__global__ __launch_bounds__(256) void featbf_kernel(const float* __restrict__ in,
                                                     __nv_bfloat16* __restrict__ Fh,
                                                     __nv_bfloat16* __restrict__ Fl) {
    __shared__ __align__(16) unsigned short sh[256 * 9];
    __shared__ __align__(16) unsigned short sl[256 * 9];
    int tid = threadIdx.x;
    int idx = blockIdx.x * 256 + tid;
    float v[9];
    kan_feat(in[idx], v);
#pragma unroll
    for (int j = 0; j < 9; j++) {
        __nv_bfloat16 h = __float2bfloat16(v[j]);
        sh[tid * 9 + j] = __bfloat16_as_ushort(h);
        sl[tid * 9 + j] = __bfloat16_as_ushort(__float2bfloat16(v[j] - __bfloat162float(h)));
    }
    __syncthreads();
    const uint4* s4h = reinterpret_cast<const uint4*>(sh);
    const uint4* s4l = reinterpret_cast<const uint4*>(sl);
    uint4* gh = reinterpret_cast<uint4*>(Fh + (size_t)blockIdx.x * 2304);
    uint4* gl = reinterpret_cast<uint4*>(Fl + (size_t)blockIdx.x * 2304);
    for (int k = tid; k < 288; k += 256) {
        gh[k] = s4h[k];
        gl[k] = s4l[k];
    }
}

// ---------------- weight packing (smem-staged vectorized writes) ----------------
__global__ __launch_bounds__(256) void packbf_kernel(const float* __restrict__ bw,
                                                     const float* __restrict__ sw,
                                                     const float* __restrict__ sc,
                                                     __nv_bfloat16* __restrict__ Wh,
                                                     __nv_bfloat16* __restrict__ Wl) {
    __shared__ __align__(16) unsigned short sh[256 * 9];
    __shared__ __align__(16) unsigned short sl[256 * 9];
    int tid = threadIdx.x;
    int idx = blockIdx.x * 256 + tid; // (e*N + n)*IN + i
    float vals[9];
    vals[0] = bw[idx];
    float s = sc[idx];
    const float* sp = sw + (size_t)idx * C_SZ;
#pragma unroll
    for (int c = 0; c < C_SZ; c++) vals[1 + c] = sp[c] * s;
#pragma unroll
    for (int j = 0; j < 9; j++) {
        __nv_bfloat16 h = __float2bfloat16(vals[j]);
        sh[tid * 9 + j] = __bfloat16_as_ushort(h);
        sl[tid * 9 + j] = __bfloat16_as_ushort(__float2bfloat16(vals[j] - __bfloat162float(h)));
    }
    __syncthreads();
    const uint4* s4h = reinterpret_cast<const uint4*>(sh);
    const uint4* s4l = reinterpret_cast<const uint4*>(sl);
    uint4* gh = reinterpret_cast<uint4*>(Wh + (size_t)blockIdx.x * 2304);
    uint4* gl = reinterpret_cast<uint4*>(Wl + (size_t)blockIdx.x * 2304);
    for (int k = tid; k < 288; k += 256) {
        gh[k] = s4h[k];
        gl[k] = s4l[k];
    }
}

// ---------------- GEMM common ----------------
#define BM 128
#define BN 128
#define BK 64
#define NCHUNK (KF / BK)        // 72
#define PLANE_BYTES 16384       // 128 rows * 128 B
#define STAGE_BYTES (4 * PLANE_BYTES)
#define NSTAGE 3
#define GEMM_SMEM (NSTAGE * STAGE_BYTES)   // 196608
#define HS_STRIDE 130

__device__ __forceinline__ void load_chunk_ptrs(uint32_t sb, int stage_idx,
                                                const __nv_bfloat16* pA_h,
                                                const __nv_bfloat16* pA_l,
                                                const __nv_bfloat16* pB_h,
                                                const __nv_bfloat16* pB_l,
                                                int k0, int tid) {
    uint32_t base = sb + (uint32_t)stage_idx * STAGE_BYTES;
    const __nv_bfloat16* gp[4] = { pA_h, pA_l, pB_h, pB_l };
#pragma unroll
    for (int p = 0; p < 4; p++) {
        const __nv_bfloat16* g = gp[p];
        uint32_t pb = base + p * PLANE_BYTES;
#pragma unroll
        for (int it = 0; it < 4; it++) {
            int idx = tid + it * 256;
            int r = idx >> 3;
            int kk = idx & 7;
            uint32_t off = (uint32_t)(r * 128 + kk * 16);
            cp16(pb + (off ^ ((off >> 3) & 0x70)),
                 g + (size_t)r * KF + k0 + kk * 8);
        }
    }
    cp_commit();
}

// run MMAs for one resident chunk stage
struct WarpCtx {
    uint32_t a_row[4], a_xor[4], a_kb;
    uint32_t b_row[2], b_xor[2], b_kb;
};

__device__ __forceinline__ void init_warp_ctx(WarpCtx& w, int warp_m, int warp_n, int lane) {
#pragma unroll
    for (int mt = 0; mt < 4; mt++) {
        int r = warp_m * 64 + mt * 16 + (lane & 15);
        w.a_row[mt] = (uint32_t)(r * 128);
        w.a_xor[mt] = (uint32_t)((r & 7) << 4);
    }
    w.a_kb = (uint32_t)((lane >> 4) << 4);
#pragma unroll
    for (int p = 0; p < 2; p++) {
        int r = warp_n * 32 + p * 16 + ((lane >> 4) << 3) + (lane & 7);
        w.b_row[p] = (uint32_t)(r * 128);
        w.b_xor[p] = (uint32_t)((r & 7) << 4);
    }
    w.b_kb = (uint32_t)(((lane >> 3) & 1) << 4);
}

__device__ __forceinline__ void chunk_mma(const WarpCtx& w, uint32_t stage,
                                          float acc[4][4][4]) {
    uint32_t pAh = stage, pAl = stage + PLANE_BYTES;
    uint32_t pBh = stage + 2 * PLANE_BYTES, pBl = stage + 3 * PLANE_BYTES;
#pragma unroll
    for (int ks = 0; ks < 4; ks++) {
        uint32_t kb = (uint32_t)(ks * 32);
        uint32_t aH[4][4], aL[4][4], bH[4][2], bL[4][2];
#pragma unroll
        for (int mt = 0; mt < 4; mt++) {
            uint32_t off = w.a_row[mt] + ((kb + w.a_kb) ^ w.a_xor[mt]);
            ldm_x4(aH[mt], pAh + off);
            ldm_x4(aL[mt], pAl + off);
        }
#pragma unroll
        for (int p = 0; p < 2; p++) {
            uint32_t off = w.b_row[p] + ((kb + w.b_kb) ^ w.b_xor[p]);
            uint32_t r4[4];
            ldm_x4(r4, pBh + off);
            bH[2 * p][0] = r4[0]; bH[2 * p][1] = r4[1];
            bH[2 * p + 1][0] = r4[2]; bH[2 * p + 1][1] = r4[3];
            ldm_x4(r4, pBl + off);
            bL[2 * p][0] = r4[0]; bL[2 * p][1] = r4[1];
            bL[2 * p + 1][0] = r4[2]; bL[2 * p + 1][1] = r4[3];
        }
#pragma unroll
        for (int mt = 0; mt < 4; mt++)
#pragma unroll
            for (int nt = 0; nt < 4; nt++) {
                mma_bf16(acc[mt][nt], aH[mt], bH[nt]);
                mma_bf16(acc[mt][nt], aH[mt], bL[nt]);
                mma_bf16(acc[mt][nt], aL[mt], bH[nt]);
            }
    }
}

// ---------------- GEMM1 (all experts, fused featurize+gate epilogue) ----------------
__global__ __launch_bounds__(256, 1) void kan_gemm1(
    const __nv_bfloat16* __restrict__ F1h, const __nv_bfloat16* __restrict__ F1l,
    const __nv_bfloat16* __restrict__ W1h, const __nv_bfloat16* __restrict__ W1l,
    __nv_bfloat16* __restrict__ F2h, __nv_bfloat16* __restrict__ F2l,
    const float* __restrict__ gate)
{
    extern __shared__ char smem[];
    uint32_t sb = smem_u32(smem);
    const int tid = threadIdx.x;
    const int wid = tid >> 5, lane = tid & 31;
    const int warp_m = wid & 1, warp_n = wid >> 1;
    const int bm = blockIdx.y * BM, bn = blockIdx.x * BN;
    const int e = blockIdx.z;

    const __nv_bfloat16* pAh = F1h + (size_t)bm * KF;
    const __nv_bfloat16* pAl = F1l + (size_t)bm * KF;
    const __nv_bfloat16* pBh = W1h + (size_t)e * H_SZ * KF + (size_t)bn * KF;
    const __nv_bfloat16* pBl = W1l + (size_t)e * H_SZ * KF + (size_t)bn * KF;

    WarpCtx w;
    init_warp_ctx(w, warp_m, warp_n, lane);

    float acc[4][4][4];
#pragma unroll
    for (int mt = 0; mt < 4; mt++)
#pragma unroll
        for (int nt = 0; nt < 4; nt++)
#pragma unroll
            for (int j = 0; j < 4; j++) acc[mt][nt][j] = 0.f;

    load_chunk_ptrs(sb, 0, pAh, pAl, pBh, pBl, 0, tid);
    load_chunk_ptrs(sb, 1, pAh, pAl, pBh, pBl, BK, tid);

    for (int c = 0; c < NCHUNK; c++) {
        if (c + 2 < NCHUNK) cp_wait<1>(); else cp_wait<0>();
        __syncthreads();
        chunk_mma(w, sb + (uint32_t)(c % NSTAGE) * STAGE_BYTES, acc);
        if (c + 2 < NCHUNK)
            load_chunk_ptrs(sb, (c + 2) % NSTAGE, pAh, pAl, pBh, pBl, (c + 2) * BK, tid);
    }

    // ---- fused featurize + gate-scale epilogue ----
    __syncthreads();
    float* Hs = reinterpret_cast<float*>(smem);
    const int gn0 = warp_n * 32;
#pragma unroll
    for (int mt = 0; mt < 4; mt++) {
        int r0 = warp_m * 64 + mt * 16 + (lane >> 2);
        int r1 = r0 + 8;
#pragma unroll
        for (int nt = 0; nt < 4; nt++) {
            int cc = gn0 + nt * 8 + (lane & 3) * 2;
            Hs[r0 * HS_STRIDE + cc]     = acc[mt][nt][0];
            Hs[r0 * HS_STRIDE + cc + 1] = acc[mt][nt][1];
            Hs[r1 * HS_STRIDE + cc]     = acc[mt][nt][2];
            Hs[r1 * HS_STRIDE + cc + 1] = acc[mt][nt][3];
        }
    }
    __syncthreads();
    const int row = tid >> 1;
    const int half = tid & 1;
    const float* hrow = Hs + row * HS_STRIDE + half * 64;
    const float gv = gate[(size_t)(bm + row) * E_SZ + e];
    size_t gbase = (size_t)e * FSTRIDE + (size_t)(bm + row) * KF + ((size_t)bn + half * 64) * 9;
    uint4* gh = reinterpret_cast<uint4*>(F2h + gbase);
    uint4* gl = reinterpret_cast<uint4*>(F2l + gbase);
#pragma unroll
    for (int b = 0; b < 8; b++) {
        uint32_t hi32[36], lo32[36];
#pragma unroll
        for (int el = 0; el < 8; el++) {
            float f[9];
            kan_feat(hrow[b * 8 + el], f);
#pragma unroll
            for (int j = 0; j < 9; j++) {
                int p = el * 9 + j;
                float v = f[j] * gv;
                __nv_bfloat16 h = __float2bfloat16(v);
                uint32_t hb = (uint32_t)__bfloat16_as_ushort(h);
                uint32_t lb = (uint32_t)__bfloat16_as_ushort(
                    __float2bfloat16(v - __bfloat162float(h)));
                if ((p & 1) == 0) { hi32[p >> 1] = hb; lo32[p >> 1] = lb; }
                else { hi32[p >> 1] |= hb << 16; lo32[p >> 1] |= lb << 16; }
            }
        }
#pragma unroll
        for (int q = 0; q < 9; q++) {
            gh[b * 9 + q] = make_uint4(hi32[q * 4], hi32[q * 4 + 1],
                                       hi32[q * 4 + 2], hi32[q * 4 + 3]);
            gl[b * 9 + q] = make_uint4(lo32[q * 4], lo32[q * 4 + 1],
                                       lo32[q * 4 + 2], lo32[q * 4 + 3]);
        }
    }
}

// ---------------- GEMM2 (fused over all experts, K = 8*4608) ----------------
#define NCHUNK2 (E_SZ * NCHUNK)   // 576

__global__ __launch_bounds__(256, 1) void kan_gemm2(
    const __nv_bfloat16* __restrict__ F2h, const __nv_bfloat16* __restrict__ F2l,
    const __nv_bfloat16* __restrict__ W2h, const __nv_bfloat16* __restrict__ W2l,
    float* __restrict__ Cout)
{
    extern __shared__ char smem[];
    uint32_t sb = smem_u32(smem);
    const int tid = threadIdx.x;
    const int wid = tid >> 5, lane = tid & 31;
    const int warp_m = wid & 1, warp_n = wid >> 1;
    const int bm = blockIdx.y * BM, bn = blockIdx.x * BN;

    WarpCtx w;
    init_warp_ctx(w, warp_m, warp_n, lane);

    float acc[4][4][4];
#pragma unroll
    for (int mt = 0; mt < 4; mt++)
#pragma unroll
        for (int nt = 0; nt < 4; nt++)
#pragma unroll
            for (int j = 0; j < 4; j++) acc[mt][nt][j] = 0.f;

    // prefetch helper: global chunk index cc in [0, 576)
    auto prefetch = [&](int cc, int stage_idx) {
        int e = cc / NCHUNK;          // mul-shift, cheap
        int k0 = (cc - e * NCHUNK) * BK;
        const __nv_bfloat16* pAh = F2h + (size_t)e * FSTRIDE + (size_t)bm * KF;
        const __nv_bfloat16* pAl = F2l + (size_t)e * FSTRIDE + (size_t)bm * KF;
        const __nv_bfloat16* pBh = W2h + (size_t)e * O_SZ * KF + (size_t)bn * KF;
        const __nv_bfloat16* pBl = W2l + (size_t)e * O_SZ * KF + (size_t)bn * KF;
        load_chunk_ptrs(sb, stage_idx, pAh, pAl, pBh, pBl, k0, tid);
    };

    prefetch(0, 0);
    prefetch(1, 1);

    for (int c = 0; c < NCHUNK2; c++) {
        if (c + 2 < NCHUNK2) cp_wait<1>(); else cp_wait<0>();
        __syncthreads();
        chunk_mma(w, sb + (uint32_t)(c % NSTAGE) * STAGE_BYTES, acc);
        if (c + 2 < NCHUNK2) prefetch(c + 2, (c + 2) % NSTAGE);
    }

    // ---- plain store epilogue (gate already folded into F2) ----
#pragma unroll
    for (int mt = 0; mt < 4; mt++) {
        int r0 = bm + warp_m * 64 + mt * 16 + (lane >> 2);
        int r1 = r0 + 8;
#pragma unroll
        for (int nt = 0; nt < 4; nt++) {
            int cc = bn + warp_n * 32 + nt * 8 + (lane & 3) * 2;
            *reinterpret_cast<float2*>(Cout + (size_t)r0 * 512 + cc) =
                make_float2(acc[mt][nt][0], acc[mt][nt][1]);
            *reinterpret_cast<float2*>(Cout + (size_t)r1 * 512 + cc) =
                make_float2(acc[mt][nt][2], acc[mt][nt][3]);
        }
    }
}

// ---------------- launch ----------------
extern "C" void kernel_launch(void* const* d_in, const int* in_sizes, int n_in,
                              void* d_out, int out_size) {
    const float* x         = (const float*)d_in[0];
    const float* gate_w    = (const float*)d_in[1];
    const float* gate_b    = (const float*)d_in[2];
    const float* base_w1   = (const float*)d_in[3];
    const float* spline_w1 = (const float*)d_in[4];
    const float* scaler1   = (const float*)d_in[5];
    const float* base_w2   = (const float*)d_in[6];
    const float* spline_w2 = (const float*)d_in[7];
    const float* scaler2   = (const float*)d_in[8];
    float* out = (float*)d_out;

    __nv_bfloat16 *pF1h, *pF1l, *pF2h, *pF2l, *pW1h, *pW1l, *pW2h, *pW2l;
    float *pG;
    cudaGetSymbolAddress((void**)&pF1h, g_F1h);
    cudaGetSymbolAddress((void**)&pF1l, g_F1l);
    cudaGetSymbolAddress((void**)&pF2h, g_F2h);
    cudaGetSymbolAddress((void**)&pF2l, g_F2l);
    cudaGetSymbolAddress((void**)&pW1h, g_W1h);
    cudaGetSymbolAddress((void**)&pW1l, g_W1l);
    cudaGetSymbolAddress((void**)&pW2h, g_W2h);
    cudaGetSymbolAddress((void**)&pW2l, g_W2l);
    cudaGetSymbolAddress((void**)&pG, g_gate);

    cudaFuncSetAttribute(kan_gemm1, cudaFuncAttributeMaxDynamicSharedMemorySize, GEMM_SMEM);
    cudaFuncSetAttribute(kan_gemm2, cudaFuncAttributeMaxDynamicSharedMemorySize, GEMM_SMEM);

    // 1. gate softmax
    gate_kernel<<<(B_SZ * 32 + 255) / 256, 256>>>(x, gate_w, gate_b, pG);
    // 2. pack weights
    packbf_kernel<<<E_SZ * H_SZ * I_SZ / 256, 256>>>(base_w1, spline_w1, scaler1, pW1h, pW1l);
    packbf_kernel<<<E_SZ * O_SZ * H_SZ / 256, 256>>>(base_w2, spline_w2, scaler2, pW2h, pW2l);
    // 3. featurize x
    featbf_kernel<<<B_SZ * I_SZ / 256, 256>>>(x, pF1h, pF1l);
    // 4. all experts' layer-1 GEMM + featurize+gate epilogue (one launch)
    dim3 g1(O_SZ / BN, B_SZ / BM, E_SZ); // (4, 32, 8) = 1024 CTAs
    kan_gemm1<<<g1, 256, GEMM_SMEM>>>(pF1h, pF1l, pW1h, pW1l, pF2h, pF2l, pG);
    // 5. fused layer-2 GEMM over all experts (one launch)
    dim3 g2(O_SZ / BN, B_SZ / BM);       // (4, 32) = 128 CTAs
    kan_gemm2<<<g2, 256, GEMM_SMEM>>>(pF2h, pF2l, pW2h, pW2l, out);
}